// round 3
// baseline (speedup 1.0000x reference)
#include <cuda_runtime.h>

// Problem constants (fixed by the dataset)
#define BB   512
#define TT   100
#define LL   256
#define DD   128
#define PP   9
#define NSEQ (BB*TT)      // 51200
#define KK   (2*DD)       // 256
#define NG   (4*DD)       // 512
#define MTILE 32
#define NBLK (NSEQ/MTILE) // 1600
#define XH_PAD 36         // row stride (floats) for [k][m] tile: 16B-aligned, bounded conflicts

// Scratch (no cudaMalloc allowed)
__device__ float g_wcat[KK*NG];     // [k][n]: k<128 -> w_ih[n][k], else w_hh[n][k-128]
__device__ float g_bias[NG];        // b_ih + b_hh
__device__ int   g_nids[NSEQ*PP];   // gathered path node ids per sequence
__device__ int   g_active[NSEQ];

__device__ __forceinline__ float sigf(float x)   { return 1.0f / (1.0f + __expf(-x)); }
__device__ __forceinline__ float tanhf_(float x) { return 1.0f - 2.0f / (__expf(2.0f*x) + 1.0f); }

// ---------------------------------------------------------------------------
// Kernel 1: transpose/concat weights into [k][n] layout, fuse biases
// ---------------------------------------------------------------------------
__global__ void prep_kernel(const float* __restrict__ w_ih, const float* __restrict__ w_hh,
                            const float* __restrict__ b_ih, const float* __restrict__ b_hh) {
    int idx = blockIdx.x * blockDim.x + threadIdx.x;
    if (idx < KK*NG) {
        int k = idx / NG;
        int n = idx % NG;
        g_wcat[idx] = (k < DD) ? w_ih[n*DD + k] : w_hh[n*DD + (k - DD)];
    }
    if (idx < NG) g_bias[idx] = b_ih[idx] + b_hh[idx];
}

// ---------------------------------------------------------------------------
// Kernel 2: per (b,t) argmax (first-max semantics) + active flag + path gather
// One warp per sequence.
// ---------------------------------------------------------------------------
__global__ void leaf_kernel(const float* __restrict__ cross, const int* __restrict__ paths) {
    int warp = (blockIdx.x * blockDim.x + threadIdx.x) >> 5;
    int lane = threadIdx.x & 31;
    if (warp >= NSEQ) return;
    int b = warp / TT;
    int t = warp - b * TT;
    const float* row = cross + (size_t)b * (TT*LL) + (size_t)t * LL;

    float bv = -3.0e38f;
    int   bl = 0;
    int   anyp = 0;
#pragma unroll
    for (int i = 0; i < LL/32; i++) {
        int l = lane + 32*i;            // ascending within lane -> strict '>' keeps first max
        float v = row[l];
        if (v > 0.0f) anyp = 1;
        if (v > bv) { bv = v; bl = l; }
    }
#pragma unroll
    for (int off = 16; off > 0; off >>= 1) {
        float ov = __shfl_down_sync(0xffffffffu, bv, off);
        int   ol = __shfl_down_sync(0xffffffffu, bl, off);
        if (ov > bv || (ov == bv && ol < bl)) { bv = ov; bl = ol; }
    }
    anyp = __any_sync(0xffffffffu, anyp);
    int leaf = __shfl_sync(0xffffffffu, bl, 0);

    if (lane < PP) g_nids[warp*PP + lane] = paths[((size_t)t*LL + leaf)*PP + lane];
    if (lane == 0) g_active[warp] = anyp;
}

// ---------------------------------------------------------------------------
// Kernel 3: batched LSTM. CTA = 32 sequences, 256 threads.
// Thread (hf, j): j in [0,128) = hidden dim / gate column, hf = which 16-seq half.
// Shared holds [x_t | h] transposed as xh[k][m] (k in [0,256), m in [0,32)).
// Per k: 4 weight LDG (coalesced, L2-resident) + 4 broadcast LDS.128 + 64 FFMA.
// ---------------------------------------------------------------------------
__global__ void __launch_bounds__(256, 2)
lstm_kernel(const float* __restrict__ node_emb, float* __restrict__ out) {
    __shared__ __align__(16) float xh[KK][XH_PAD];
    __shared__ int snid[MTILE*PP];
    __shared__ int sact[MTILE];

    int tid = threadIdx.x;
    int j   = tid & 127;
    int hf  = tid >> 7;
    int bt0 = blockIdx.x * MTILE;

    // zero the h region (k in [128,256))
    for (int idx = tid; idx < DD*XH_PAD; idx += 256)
        (&xh[DD][0])[idx] = 0.0f;
    // preload all path node ids + active flags
    for (int idx = tid; idx < MTILE*PP; idx += 256) {
        int m = idx / PP, p = idx - m*PP;
        snid[idx] = g_nids[(bt0 + m)*PP + p];
    }
    if (tid < MTILE) sact[tid] = g_active[bt0 + tid];
    __syncthreads();   // snid/sact/h-zero must be visible before use

    float c[16];
#pragma unroll
    for (int m = 0; m < 16; m++) c[m] = 0.0f;

    const float bi = g_bias[j];
    const float bf = g_bias[128 + j];
    const float bg = g_bias[256 + j];
    const float bo = g_bias[384 + j];

    for (int p = 0; p < PP; p++) {
        // load x_t for 32 sequences, transposed into xh[k][m]
        // (prior sync guarantees all compute reads of the x region are done)
#pragma unroll
        for (int i = 0; i < 16; i++) {
            int idx = i*256 + tid;
            int m = idx >> 7;
            int k = idx & 127;
            xh[k][m] = node_emb[(size_t)snid[m*PP + p]*DD + k];
        }
        __syncthreads();   // x + h regions ready

        float a0[16], a1[16], a2[16], a3[16];
#pragma unroll
        for (int m = 0; m < 16; m++) { a0[m]=bi; a1[m]=bf; a2[m]=bg; a3[m]=bo; }

        const float* wp = g_wcat + j;
#pragma unroll 4
        for (int k = 0; k < KK; k++) {
            float w0 = wp[k*NG];
            float w1 = wp[k*NG + 128];
            float w2 = wp[k*NG + 256];
            float w3 = wp[k*NG + 384];
            float xv[16];
            const float4* xr = (const float4*)&xh[k][hf*16];
            *(float4*)&xv[0]  = xr[0];
            *(float4*)&xv[4]  = xr[1];
            *(float4*)&xv[8]  = xr[2];
            *(float4*)&xv[12] = xr[3];
#pragma unroll
            for (int m = 0; m < 16; m++) {
                float x = xv[m];
                a0[m] = fmaf(w0, x, a0[m]);
                a1[m] = fmaf(w1, x, a1[m]);
                a2[m] = fmaf(w2, x, a2[m]);
                a3[m] = fmaf(w3, x, a3[m]);
            }
        }
        __syncthreads();   // everyone done reading h region before we overwrite it

        // elementwise gates; write new h straight into shared h region
#pragma unroll
        for (int m = 0; m < 16; m++) {
            float ig = sigf(a0[m]);
            float fg = sigf(a1[m]);
            float gg = tanhf_(a2[m]);
            float og = sigf(a3[m]);
            c[m] = fg * c[m] + ig * gg;
            xh[DD + j][hf*16 + m] = og * tanhf_(c[m]);
        }
        __syncthreads();   // h writes visible before next step's compute / final readout
    }

    // output: thread owns its own h values (it wrote them) -> read back, mask inactive
#pragma unroll
    for (int m = 0; m < 16; m++) {
        int bt = bt0 + hf*16 + m;
        float h = xh[DD + j][hf*16 + m];
        out[(size_t)bt*DD + j] = sact[hf*16 + m] ? h : 0.0f;
    }
}

// ---------------------------------------------------------------------------
extern "C" void kernel_launch(void* const* d_in, const int* in_sizes, int n_in,
                              void* d_out, int out_size) {
    const float* cross    = (const float*)d_in[0];
    const float* node_emb = (const float*)d_in[1];
    const float* w_ih     = (const float*)d_in[2];
    const float* w_hh     = (const float*)d_in[3];
    const float* b_ih     = (const float*)d_in[4];
    const float* b_hh     = (const float*)d_in[5];
    const int*   paths    = (const int*)d_in[6];
    float* out = (float*)d_out;

    prep_kernel<<<(KK*NG + 255)/256, 256>>>(w_ih, w_hh, b_ih, b_hh);
    leaf_kernel<<<(NSEQ*32 + 127)/128, 128>>>(cross, paths);
    lstm_kernel<<<NBLK, 256>>>(node_emb, out);
}

// round 4
// speedup vs baseline: 1.5225x; 1.5225x over previous
#include <cuda_runtime.h>

// Problem constants (fixed by the dataset)
#define BB   512
#define TT   100
#define LL   256
#define DD   128
#define PP   9
#define NSEQ (BB*TT)      // 51200
#define KK   (2*DD)       // 256
#define NG   (4*DD)       // 512
#define MTILE 32
#define NBLK (NSEQ/MTILE) // 1600
#define XH_PAD 36         // row stride (floats) for [k][m] tile: 16B-aligned, bounded conflicts

// Scratch (no cudaMalloc allowed)
__device__ float g_wcat[KK*NG];     // [k][n]: k<128 -> w_ih[n][k], else w_hh[n][k-128]
__device__ float g_bias[NG];        // b_ih + b_hh
__device__ int   g_nids[NSEQ*PP];   // gathered path node ids per sequence
__device__ int   g_active[NSEQ];

__device__ __forceinline__ float sigf(float x)   { return 1.0f / (1.0f + __expf(-x)); }
__device__ __forceinline__ float tanhf_(float x) { return 1.0f - 2.0f / (__expf(2.0f*x) + 1.0f); }

// ---------------------------------------------------------------------------
// Kernel 1: transpose/concat weights into [k][n] layout, fuse biases
// ---------------------------------------------------------------------------
__global__ void prep_kernel(const float* __restrict__ w_ih, const float* __restrict__ w_hh,
                            const float* __restrict__ b_ih, const float* __restrict__ b_hh) {
    int idx = blockIdx.x * blockDim.x + threadIdx.x;
    if (idx < KK*NG) {
        int k = idx / NG;
        int n = idx % NG;
        g_wcat[idx] = (k < DD) ? w_ih[n*DD + k] : w_hh[n*DD + (k - DD)];
    }
    if (idx < NG) g_bias[idx] = b_ih[idx] + b_hh[idx];
}

// ---------------------------------------------------------------------------
// Kernel 2: per (b,t) argmax (first-max semantics) + active flag + path gather
// One warp per sequence.
// ---------------------------------------------------------------------------
__global__ void leaf_kernel(const float* __restrict__ cross, const int* __restrict__ paths) {
    int warp = (blockIdx.x * blockDim.x + threadIdx.x) >> 5;
    int lane = threadIdx.x & 31;
    if (warp >= NSEQ) return;
    int b = warp / TT;
    int t = warp - b * TT;
    const float* row = cross + (size_t)b * (TT*LL) + (size_t)t * LL;

    float bv = -3.0e38f;
    int   bl = 0;
    int   anyp = 0;
#pragma unroll
    for (int i = 0; i < LL/32; i++) {
        int l = lane + 32*i;            // ascending within lane -> strict '>' keeps first max
        float v = row[l];
        if (v > 0.0f) anyp = 1;
        if (v > bv) { bv = v; bl = l; }
    }
#pragma unroll
    for (int off = 16; off > 0; off >>= 1) {
        float ov = __shfl_down_sync(0xffffffffu, bv, off);
        int   ol = __shfl_down_sync(0xffffffffu, bl, off);
        if (ov > bv || (ov == bv && ol < bl)) { bv = ov; bl = ol; }
    }
    anyp = __any_sync(0xffffffffu, anyp);
    int leaf = __shfl_sync(0xffffffffu, bl, 0);

    if (lane < PP) g_nids[warp*PP + lane] = paths[((size_t)t*LL + leaf)*PP + lane];
    if (lane == 0) g_active[warp] = anyp;
}

// ---------------------------------------------------------------------------
// Kernel 3: batched LSTM. CTA = 32 sequences, 256 threads.
// Thread (hf, j): j in [0,128) = hidden dim / gate column, hf = which 16-seq half.
// Shared holds [x_t | h] transposed as xh[k][m] (k in [0,256), m in [0,32)).
// Per k: 4 weight LDG (coalesced, L2-resident) + 4 broadcast LDS.128 + 64 FFMA.
// ---------------------------------------------------------------------------
__global__ void __launch_bounds__(256, 2)
lstm_kernel(const float* __restrict__ node_emb, float* __restrict__ out) {
    __shared__ __align__(16) float xh[KK][XH_PAD];
    __shared__ int snid[MTILE*PP];
    __shared__ int sact[MTILE];

    int tid = threadIdx.x;
    int j   = tid & 127;
    int hf  = tid >> 7;
    int bt0 = blockIdx.x * MTILE;

    // zero the h region (k in [128,256))
    for (int idx = tid; idx < DD*XH_PAD; idx += 256)
        (&xh[DD][0])[idx] = 0.0f;
    // preload all path node ids + active flags
    for (int idx = tid; idx < MTILE*PP; idx += 256) {
        int m = idx / PP, p = idx - m*PP;
        snid[idx] = g_nids[(bt0 + m)*PP + p];
    }
    if (tid < MTILE) sact[tid] = g_active[bt0 + tid];
    __syncthreads();   // snid/sact/h-zero must be visible before use

    float c[16];
#pragma unroll
    for (int m = 0; m < 16; m++) c[m] = 0.0f;

    const float bi = g_bias[j];
    const float bf = g_bias[128 + j];
    const float bg = g_bias[256 + j];
    const float bo = g_bias[384 + j];

    for (int p = 0; p < PP; p++) {
        // load x_t for 32 sequences, transposed into xh[k][m]
        // (prior sync guarantees all compute reads of the x region are done)
#pragma unroll
        for (int i = 0; i < 16; i++) {
            int idx = i*256 + tid;
            int m = idx >> 7;
            int k = idx & 127;
            xh[k][m] = node_emb[(size_t)snid[m*PP + p]*DD + k];
        }
        __syncthreads();   // x + h regions ready

        float a0[16], a1[16], a2[16], a3[16];
#pragma unroll
        for (int m = 0; m < 16; m++) { a0[m]=bi; a1[m]=bf; a2[m]=bg; a3[m]=bo; }

        const float* wp = g_wcat + j;
#pragma unroll 4
        for (int k = 0; k < KK; k++) {
            float w0 = wp[k*NG];
            float w1 = wp[k*NG + 128];
            float w2 = wp[k*NG + 256];
            float w3 = wp[k*NG + 384];
            float xv[16];
            const float4* xr = (const float4*)&xh[k][hf*16];
            *(float4*)&xv[0]  = xr[0];
            *(float4*)&xv[4]  = xr[1];
            *(float4*)&xv[8]  = xr[2];
            *(float4*)&xv[12] = xr[3];
#pragma unroll
            for (int m = 0; m < 16; m++) {
                float x = xv[m];
                a0[m] = fmaf(w0, x, a0[m]);
                a1[m] = fmaf(w1, x, a1[m]);
                a2[m] = fmaf(w2, x, a2[m]);
                a3[m] = fmaf(w3, x, a3[m]);
            }
        }
        __syncthreads();   // everyone done reading h region before we overwrite it

        // elementwise gates; write new h straight into shared h region
#pragma unroll
        for (int m = 0; m < 16; m++) {
            float ig = sigf(a0[m]);
            float fg = sigf(a1[m]);
            float gg = tanhf_(a2[m]);
            float og = sigf(a3[m]);
            c[m] = fg * c[m] + ig * gg;
            xh[DD + j][hf*16 + m] = og * tanhf_(c[m]);
        }
        __syncthreads();   // h writes visible before next step's compute / final readout
    }

    // output: thread owns its own h values (it wrote them) -> read back, mask inactive
#pragma unroll
    for (int m = 0; m < 16; m++) {
        int bt = bt0 + hf*16 + m;
        float h = xh[DD + j][hf*16 + m];
        out[(size_t)bt*DD + j] = sact[hf*16 + m] ? h : 0.0f;
    }
}

// ---------------------------------------------------------------------------
extern "C" void kernel_launch(void* const* d_in, const int* in_sizes, int n_in,
                              void* d_out, int out_size) {
    const float* cross    = (const float*)d_in[0];
    const float* node_emb = (const float*)d_in[1];
    const float* w_ih     = (const float*)d_in[2];
    const float* w_hh     = (const float*)d_in[3];
    const float* b_ih     = (const float*)d_in[4];
    const float* b_hh     = (const float*)d_in[5];
    const int*   paths    = (const int*)d_in[6];
    float* out = (float*)d_out;

    prep_kernel<<<(KK*NG + 255)/256, 256>>>(w_ih, w_hh, b_ih, b_hh);
    leaf_kernel<<<(NSEQ*32 + 127)/128, 128>>>(cross, paths);
    lstm_kernel<<<NBLK, 256>>>(node_emb, out);
}

// round 6
// speedup vs baseline: 3.6300x; 2.3843x over previous
#include <cuda_runtime.h>
#include <cuda_bf16.h>
#include <cstdint>

#define BB   512
#define TT   100
#define LL   256
#define DD   128
#define PP   9
#define NSEQ (BB*TT)
#define NG   512
#define MROWS 128
#define NBLK (NSEQ/MROWS)   // 400
#define NTHR 256
#define ROWB  272            // padded row stride bytes (128 bf16 -> 136 bf16)
#define CHUNK (128*ROWB)     // 34816 bytes per W chunk
#define NCHUNKS 12

// SMEM layout (dynamic)
#define SM_AX   0
#define SM_AHI  34816
#define SM_ALO  69632
#define SM_W    104448       // 2 x CHUNK -> ends 174080
#define SM_BIAS 174080       // 2048
#define SM_NID  176128       // 4608
#define SM_ACT  180736       // 512
#define SM_MBAR 181248       // 16
#define SMEM_SZ 181504

__device__ __align__(128) unsigned char g_Bimg[NCHUNKS*CHUNK];
__device__ float g_bias[NG];
__device__ int   g_nids[NSEQ*PP];
__device__ int   g_active[NSEQ];

__device__ __forceinline__ float sigf(float x)   { return 1.0f / (1.0f + __expf(-x)); }
__device__ __forceinline__ float tanhf_(float x) { return 1.0f - 2.0f / (__expf(2.0f*x) + 1.0f); }

__device__ __forceinline__ uint32_t smem_u32(const void* p) {
    uint32_t a;
    asm("{ .reg .u64 t; cvta.to.shared.u64 t, %1; cvt.u32.u64 %0, t; }" : "=r"(a) : "l"(p));
    return a;
}
__device__ __forceinline__ void mbar_init(uint32_t mbar, uint32_t cnt) {
    asm volatile("mbarrier.init.shared.b64 [%0], %1;" :: "r"(mbar), "r"(cnt) : "memory");
}
__device__ __forceinline__ void mbar_expect_tx(uint32_t mbar, uint32_t bytes) {
    asm volatile("mbarrier.arrive.expect_tx.shared.b64 _, [%0], %1;" :: "r"(mbar), "r"(bytes) : "memory");
}
__device__ __forceinline__ void mbar_wait(uint32_t mbar, uint32_t ph) {
    asm volatile(
        "{\n\t.reg .pred P;\n\tLW_%=:\n\t"
        "mbarrier.try_wait.parity.acquire.cta.shared::cta.b64 P, [%0], %1, 0x989680;\n\t"
        "@P bra LD_%=;\n\tbra LW_%=;\n\tLD_%=:\n\t}"
        :: "r"(mbar), "r"(ph) : "memory");
}
__device__ __forceinline__ void bulk_g2s(uint32_t dst, const void* src, uint32_t bytes, uint32_t mbar) {
    asm volatile(
        "cp.async.bulk.shared::cluster.global.mbarrier::complete_tx::bytes [%0], [%1], %2, [%3];"
        :: "r"(dst), "l"(src), "r"(bytes), "r"(mbar) : "memory");
}
__device__ __forceinline__ void mma16816(float* d, const uint32_t* a, const uint32_t* b) {
    asm volatile(
        "mma.sync.aligned.m16n8k16.row.col.f32.bf16.bf16.f32 "
        "{%0,%1,%2,%3}, {%4,%5,%6,%7}, {%8,%9}, {%0,%1,%2,%3};"
        : "+f"(d[0]), "+f"(d[1]), "+f"(d[2]), "+f"(d[3])
        : "r"(a[0]), "r"(a[1]), "r"(a[2]), "r"(a[3]), "r"(b[0]), "r"(b[1]));
}

// One [128m x 128n x 128k] product-accumulate. A at aoff, W at woff (both padded ROWB).
__device__ __forceinline__ void gemm_pass(const char* __restrict__ smem,
                                          uint32_t aoff, uint32_t woff,
                                          int g, int tg, int mw, int nw,
                                          float d[4][4][4]) {
    const char* A = smem + aoff;
    const char* W = smem + woff;
#pragma unroll
    for (int k8 = 0; k8 < 8; k8++) {
        const int kb = (k8*16 + tg*2) * 2;
        uint32_t a[4][4], b[4][2];
#pragma unroll
        for (int mi = 0; mi < 4; mi++) {
            const int r0 = mw*64 + mi*16 + g;
            a[mi][0] = *(const uint32_t*)(A + r0*ROWB + kb);
            a[mi][1] = *(const uint32_t*)(A + (r0+8)*ROWB + kb);
            a[mi][2] = *(const uint32_t*)(A + r0*ROWB + kb + 16);
            a[mi][3] = *(const uint32_t*)(A + (r0+8)*ROWB + kb + 16);
        }
#pragma unroll
        for (int ni = 0; ni < 4; ni++) {
            const int wr = nw*32 + ni*8 + g;
            b[ni][0] = *(const uint32_t*)(W + wr*ROWB + kb);
            b[ni][1] = *(const uint32_t*)(W + wr*ROWB + kb + 16);
        }
#pragma unroll
        for (int mi = 0; mi < 4; mi++)
#pragma unroll
            for (int ni = 0; ni < 4; ni++)
                mma16816(d[mi][ni], a[mi], b[ni]);
    }
}

// ---------------------------------------------------------------------------
// prep: build W image. chunk = q*3 + part (0:Wih, 1:Whh_hi, 2:Whh_lo).
// Within a chunk: row n = (j&31)*4 + gate  (gate-interleaved), col k, 272B rows.
// ---------------------------------------------------------------------------
__global__ void prep_kernel(const float* __restrict__ w_ih, const float* __restrict__ w_hh,
                            const float* __restrict__ b_ih, const float* __restrict__ b_hh) {
    int idx = blockIdx.x * blockDim.x + threadIdx.x;
    if (idx < NG) g_bias[idx] = b_ih[idx] + b_hh[idx];
    if (idx >= 3 * NG * DD) return;
    int part = idx >> 16;          // 65536 = 512*128
    int rem  = idx & 65535;
    int r = rem >> 7;              // 0..511 (gate*128 + j)
    int k = rem & 127;
    int gate = r >> 7, j = r & 127;
    int q = j >> 5;
    int n = ((j & 31) << 2) | gate;
    __nv_bfloat16 v;
    if (part == 0) {
        v = __float2bfloat16(w_ih[r * DD + k]);
    } else {
        float w = w_hh[r * DD + k];
        __nv_bfloat16 hi = __float2bfloat16(w);
        v = (part == 1) ? hi : __float2bfloat16(w - __bfloat162float(hi));
    }
    *(__nv_bfloat16*)((char*)g_Bimg + (q*3 + part)*CHUNK + n*ROWB + k*2) = v;
}

// ---------------------------------------------------------------------------
__global__ void leaf_kernel(const float* __restrict__ cross, const int* __restrict__ paths) {
    int warp = (blockIdx.x * blockDim.x + threadIdx.x) >> 5;
    int lane = threadIdx.x & 31;
    if (warp >= NSEQ) return;
    int b = warp / TT;
    int t = warp - b * TT;
    const float* row = cross + (size_t)b * (TT*LL) + (size_t)t * LL;
    float bv = -3.0e38f; int bl = 0; int anyp = 0;
#pragma unroll
    for (int i = 0; i < LL/32; i++) {
        int l = lane + 32*i;
        float v = row[l];
        if (v > 0.0f) anyp = 1;
        if (v > bv) { bv = v; bl = l; }
    }
#pragma unroll
    for (int off = 16; off > 0; off >>= 1) {
        float ov = __shfl_down_sync(0xffffffffu, bv, off);
        int   ol = __shfl_down_sync(0xffffffffu, bl, off);
        if (ov > bv || (ov == bv && ol < bl)) { bv = ov; bl = ol; }
    }
    anyp = __any_sync(0xffffffffu, anyp);
    int leaf = __shfl_sync(0xffffffffu, bl, 0);
    if (lane < PP) g_nids[warp*PP + lane] = paths[((size_t)t*LL + leaf)*PP + lane];
    if (lane == 0) g_active[warp] = anyp;
}

// ---------------------------------------------------------------------------
__global__ void __launch_bounds__(NTHR, 1)
lstm_mma(const float* __restrict__ node_emb, float* __restrict__ out) {
    extern __shared__ __align__(16) char smem[];
    const uint32_t sb = smem_u32(smem);
    const int tid  = threadIdx.x;
    const int wid  = tid >> 5, lane = tid & 31;
    const int g    = lane >> 2, tg = lane & 3;
    const int mw   = wid >> 2, nw = wid & 3;
    const int bt0  = blockIdx.x * MROWS;

    int* snid   = (int*)(smem + SM_NID);
    int* sact   = (int*)(smem + SM_ACT);
    float* sbias = (float*)(smem + SM_BIAS);
    for (int i = tid; i < MROWS*PP; i += NTHR) snid[i] = g_nids[bt0*PP + i];
    for (int i = tid; i < MROWS; i += NTHR)    sact[i] = g_active[bt0 + i];
    for (int i = tid; i < NG; i += NTHR)       sbias[i] = g_bias[i];
    if (tid == 0) { mbar_init(sb + SM_MBAR, 1); mbar_init(sb + SM_MBAR + 8, 1); }
    __syncthreads();

    float creg[4][16], hk[4][16];
#pragma unroll
    for (int q = 0; q < 4; q++)
#pragma unroll
        for (int i = 0; i < 16; i++) creg[q][i] = 0.0f;

    int ccnt = 0;     // consumed chunk count (all threads)
    int icnt = 0;     // issued chunk count (tid0 only meaningful)

    const int rbase = mw*64 + ((tg & 1) ? 8 : 0) + g;   // epilogue row base

    for (int p = 0; p < PP; p++) {
        // ---- gather x_p into A_x (row-major, ROWB-padded) ----
#pragma unroll
        for (int i = 0; i < 16; i++) {
            int idx = i * NTHR + tid;          // 4096 float4 items
            int mm = idx >> 5, kq = (idx & 31) << 2;
            const float4 v = *(const float4*)(node_emb + (size_t)snid[mm*PP + p]*DD + kq);
            __nv_bfloat162 a = __floats2bfloat162_rn(v.x, v.y);
            __nv_bfloat162 b = __floats2bfloat162_rn(v.z, v.w);
            uint2 pk; pk.x = *(uint32_t*)&a; pk.y = *(uint32_t*)&b;
            *(uint2*)(smem + SM_AX + mm*ROWB + kq*2) = pk;
        }
        __syncthreads();   // x visible; prev-step h scatter visible; buffers free

        const int L = (p == 0) ? 4 : 12;
        float d[4][4][4];

        for (int ci = 0; ci < L; ci++) {
            const int part = (p == 0) ? 0 : (ci % 3);
            if (tid == 0) {
                if (ci == 0) {
                    uint32_t mb = sb + SM_MBAR + 8*(icnt & 1);
                    mbar_expect_tx(mb, CHUNK);
                    bulk_g2s(sb + SM_W + (icnt & 1)*CHUNK, (const char*)g_Bimg, CHUNK, mb);
                    icnt++;
                }
                if (ci + 1 < L) {
                    int cid = (p == 0) ? (ci + 1)*3 : (ci + 1);
                    uint32_t mb = sb + SM_MBAR + 8*(icnt & 1);
                    mbar_expect_tx(mb, CHUNK);
                    bulk_g2s(sb + SM_W + (icnt & 1)*CHUNK,
                             (const char*)g_Bimg + (size_t)cid*CHUNK, CHUNK, mb);
                    icnt++;
                }
            }
            mbar_wait(sb + SM_MBAR + 8*(ccnt & 1), (ccnt >> 1) & 1);
            const uint32_t wb = SM_W + (ccnt & 1)*CHUNK;
            ccnt++;

            if (part == 0) {
#pragma unroll
                for (int mi = 0; mi < 4; mi++)
#pragma unroll
                    for (int ni = 0; ni < 4; ni++)
#pragma unroll
                        for (int e = 0; e < 4; e++) d[mi][ni][e] = 0.0f;
                gemm_pass(smem, SM_AX, wb, g, tg, mw, nw, d);
            } else if (part == 1) {
                gemm_pass(smem, SM_AHI, wb, g, tg, mw, nw, d);
                gemm_pass(smem, SM_ALO, wb, g, tg, mw, nw, d);
            } else {
                gemm_pass(smem, SM_AHI, wb, g, tg, mw, nw, d);
            }

            const bool qdone = (p == 0) || (part == 2);
            if (qdone) {
                const int q = (p == 0) ? ci : (ci / 3);
#pragma unroll
                for (int ni = 0; ni < 4; ni++) {
                    const int j = q*32 + nw*8 + ni*2 + (tg >> 1);
                    const float bi = sbias[j],       bfv = sbias[128 + j];
                    const float bg = sbias[256 + j], bo  = sbias[384 + j];
#pragma unroll
                    for (int mi = 0; mi < 4; mi++) {
                        float d0 = d[mi][ni][0], d1 = d[mi][ni][1];
                        float d2 = d[mi][ni][2], d3 = d[mi][ni][3];
                        float s0 = __shfl_xor_sync(0xffffffffu, d0, 1);
                        float s1 = __shfl_xor_sync(0xffffffffu, d1, 1);
                        float s2 = __shfl_xor_sync(0xffffffffu, d2, 1);
                        float s3 = __shfl_xor_sync(0xffffffffu, d3, 1);
                        float gi, gf, gg, go;
                        if ((tg & 1) == 0) { gi = d0; gf = d1; gg = s0; go = s1; }
                        else               { gi = s2; gf = s3; gg = d2; go = d3; }
                        float& cc = creg[q][mi*4 + ni];
                        cc = sigf(gf + bfv) * cc + sigf(gi + bi) * tanhf_(gg + bg);
                        hk[q][mi*4 + ni] = sigf(go + bo) * tanhf_(cc);
                    }
                }
            }
            __syncthreads();   // frees this W buffer for re-issue
        }

        if (p < PP - 1) {
            // scatter h -> A_hi / A_lo (bf16) for next step
#pragma unroll
            for (int q = 0; q < 4; q++)
#pragma unroll
                for (int ni = 0; ni < 4; ni++) {
                    const int j = q*32 + nw*8 + ni*2 + (tg >> 1);
#pragma unroll
                    for (int mi = 0; mi < 4; mi++) {
                        const int r = rbase + mi*16;
                        float h = hk[q][mi*4 + ni];
                        __nv_bfloat16 hi = __float2bfloat16(h);
                        *(__nv_bfloat16*)(smem + SM_AHI + r*ROWB + j*2) = hi;
                        *(__nv_bfloat16*)(smem + SM_ALO + r*ROWB + j*2) =
                            __float2bfloat16(h - __bfloat162float(hi));
                    }
                }
            // visibility guaranteed by the __syncthreads after next step's x-gather
        }
    }

    // ---- final output: stage fp32 h (over A_x/A_hi region), then coalesced out ----
    float* stage = (float*)smem;
#pragma unroll
    for (int q = 0; q < 4; q++)
#pragma unroll
        for (int ni = 0; ni < 4; ni++) {
            const int j = q*32 + nw*8 + ni*2 + (tg >> 1);
#pragma unroll
            for (int mi = 0; mi < 4; mi++)
                stage[(rbase + mi*16)*129 + j] = hk[q][mi*4 + ni];
        }
    __syncthreads();
#pragma unroll 4
    for (int i = tid; i < MROWS*DD; i += NTHR) {
        int r = i >> 7, k = i & 127;
        out[(size_t)(bt0 + r)*DD + k] = sact[r] ? stage[r*129 + k] : 0.0f;
    }
}

// ---------------------------------------------------------------------------
extern "C" void kernel_launch(void* const* d_in, const int* in_sizes, int n_in,
                              void* d_out, int out_size) {
    const float* cross    = (const float*)d_in[0];
    const float* node_emb = (const float*)d_in[1];
    const float* w_ih     = (const float*)d_in[2];
    const float* w_hh     = (const float*)d_in[3];
    const float* b_ih     = (const float*)d_in[4];
    const float* b_hh     = (const float*)d_in[5];
    const int*   paths    = (const int*)d_in[6];
    float* out = (float*)d_out;

    cudaFuncSetAttribute(lstm_mma, cudaFuncAttributeMaxDynamicSharedMemorySize, SMEM_SZ);
    prep_kernel<<<(3*NG*DD + 255)/256, 256>>>(w_ih, w_hh, b_ih, b_hh);
    leaf_kernel<<<(NSEQ*32 + 127)/128, 128>>>(cross, paths);
    lstm_mma<<<NBLK, NTHR, SMEM_SZ>>>(node_emb, out);
}

// round 7
// speedup vs baseline: 4.7114x; 1.2979x over previous
#include <cuda_runtime.h>
#include <cuda_bf16.h>
#include <cstdint>

#define BB   512
#define TT   100
#define LL   256
#define DD   128
#define PP   9
#define NSEQ (BB*TT)
#define NG   512
#define MROWS 128
#define NBLK (NSEQ/MROWS)   // 400
#define NTHR 512
#define ROWB  272            // padded row stride bytes
#define CHUNK (128*ROWB)     // 34816 bytes
#define NCHUNKS 12

// SMEM layout (dynamic)
#define SM_AX   0
#define SM_AHI  34816
#define SM_ALO  69632
#define SM_W    104448       // 2 x CHUNK
#define SM_BIAS 174080
#define SM_NID  176128
#define SM_ACT  180736
#define SM_MBAR 181248
#define SMEM_SZ 181504

__device__ __align__(128) unsigned char g_Bimg[NCHUNKS*CHUNK];
__device__ float g_bias[NG];
__device__ int   g_nids[NSEQ*PP];
__device__ int   g_active[NSEQ];

__device__ __forceinline__ float sigf(float x)   { return 1.0f / (1.0f + __expf(-x)); }
__device__ __forceinline__ float tanhf_(float x) { return 1.0f - 2.0f / (__expf(2.0f*x) + 1.0f); }

__device__ __forceinline__ uint32_t smem_u32(const void* p) {
    uint32_t a;
    asm("{ .reg .u64 t; cvta.to.shared.u64 t, %1; cvt.u32.u64 %0, t; }" : "=r"(a) : "l"(p));
    return a;
}
__device__ __forceinline__ void mbar_init(uint32_t mbar, uint32_t cnt) {
    asm volatile("mbarrier.init.shared.b64 [%0], %1;" :: "r"(mbar), "r"(cnt) : "memory");
}
__device__ __forceinline__ void mbar_expect_tx(uint32_t mbar, uint32_t bytes) {
    asm volatile("mbarrier.arrive.expect_tx.shared.b64 _, [%0], %1;" :: "r"(mbar), "r"(bytes) : "memory");
}
__device__ __forceinline__ void mbar_wait(uint32_t mbar, uint32_t ph) {
    asm volatile(
        "{\n\t.reg .pred P;\n\tLW_%=:\n\t"
        "mbarrier.try_wait.parity.acquire.cta.shared::cta.b64 P, [%0], %1, 0x989680;\n\t"
        "@P bra LD_%=;\n\tbra LW_%=;\n\tLD_%=:\n\t}"
        :: "r"(mbar), "r"(ph) : "memory");
}
__device__ __forceinline__ void bulk_g2s(uint32_t dst, const void* src, uint32_t bytes, uint32_t mbar) {
    asm volatile(
        "cp.async.bulk.shared::cluster.global.mbarrier::complete_tx::bytes [%0], [%1], %2, [%3];"
        :: "r"(dst), "l"(src), "r"(bytes), "r"(mbar) : "memory");
}
__device__ __forceinline__ void mma16816(float* d, const uint32_t* a, const uint32_t* b) {
    asm volatile(
        "mma.sync.aligned.m16n8k16.row.col.f32.bf16.bf16.f32 "
        "{%0,%1,%2,%3}, {%4,%5,%6,%7}, {%8,%9}, {%0,%1,%2,%3};"
        : "+f"(d[0]), "+f"(d[1]), "+f"(d[2]), "+f"(d[3])
        : "r"(a[0]), "r"(a[1]), "r"(a[2]), "r"(a[3]), "r"(b[0]), "r"(b[1]));
}
__device__ __forceinline__ void ldsm4(uint32_t* r, uint32_t addr) {
    asm volatile("ldmatrix.sync.aligned.m8n8.x4.shared.b16 {%0,%1,%2,%3}, [%4];"
        : "=r"(r[0]), "=r"(r[1]), "=r"(r[2]), "=r"(r[3]) : "r"(addr));
}

// One [64m x 16n x 128k] warp product-accumulate.
// abase: smem addr of A tile + per-lane ldmatrix offset (mi=0,k8=0).
// W: generic pointer to W chunk. d[mi][ni][e].
__device__ __forceinline__ void gemm_pass(uint32_t abase, const char* __restrict__ W,
                                          int nw, int g, int tg, float d[4][2][4]) {
#pragma unroll
    for (int k8 = 0; k8 < 8; k8++) {
        uint32_t a[4][4], b[2][2];
#pragma unroll
        for (int mi = 0; mi < 4; mi++)
            ldsm4(a[mi], abase + mi*(16*ROWB) + k8*32);
        const int kb = (k8*16 + tg*2) * 2;
#pragma unroll
        for (int ni = 0; ni < 2; ni++) {
            const char* wr = W + (nw*16 + ni*8 + g)*ROWB + kb;
            b[ni][0] = *(const uint32_t*)wr;
            b[ni][1] = *(const uint32_t*)(wr + 16);
        }
#pragma unroll
        for (int mi = 0; mi < 4; mi++)
#pragma unroll
            for (int ni = 0; ni < 2; ni++)
                mma16816(d[mi][ni], a[mi], b[ni]);
    }
}

// ---------------------------------------------------------------------------
// prep: chunk = q*3 + part (0:Wih, 1:Whh_hi, 2:Whh_lo); row n=(j&31)*4+gate, 272B rows
// ---------------------------------------------------------------------------
__global__ void prep_kernel(const float* __restrict__ w_ih, const float* __restrict__ w_hh,
                            const float* __restrict__ b_ih, const float* __restrict__ b_hh) {
    int idx = blockIdx.x * blockDim.x + threadIdx.x;
    if (idx < NG) g_bias[idx] = b_ih[idx] + b_hh[idx];
    if (idx >= 3 * NG * DD) return;
    int part = idx >> 16;
    int rem  = idx & 65535;
    int r = rem >> 7;
    int k = rem & 127;
    int gate = r >> 7, j = r & 127;
    int q = j >> 5;
    int n = ((j & 31) << 2) | gate;
    __nv_bfloat16 v;
    if (part == 0) {
        v = __float2bfloat16(w_ih[r * DD + k]);
    } else {
        float w = w_hh[r * DD + k];
        __nv_bfloat16 hi = __float2bfloat16(w);
        v = (part == 1) ? hi : __float2bfloat16(w - __bfloat162float(hi));
    }
    *(__nv_bfloat16*)((char*)g_Bimg + (q*3 + part)*CHUNK + n*ROWB + k*2) = v;
}

// ---------------------------------------------------------------------------
__global__ void leaf_kernel(const float* __restrict__ cross, const int* __restrict__ paths) {
    int warp = (blockIdx.x * blockDim.x + threadIdx.x) >> 5;
    int lane = threadIdx.x & 31;
    if (warp >= NSEQ) return;
    int b = warp / TT;
    int t = warp - b * TT;
    const float* row = cross + (size_t)b * (TT*LL) + (size_t)t * LL;
    float bv = -3.0e38f; int bl = 0; int anyp = 0;
#pragma unroll
    for (int i = 0; i < LL/32; i++) {
        int l = lane + 32*i;
        float v = row[l];
        if (v > 0.0f) anyp = 1;
        if (v > bv) { bv = v; bl = l; }
    }
#pragma unroll
    for (int off = 16; off > 0; off >>= 1) {
        float ov = __shfl_down_sync(0xffffffffu, bv, off);
        int   ol = __shfl_down_sync(0xffffffffu, bl, off);
        if (ov > bv || (ov == bv && ol < bl)) { bv = ov; bl = ol; }
    }
    anyp = __any_sync(0xffffffffu, anyp);
    int leaf = __shfl_sync(0xffffffffu, bl, 0);
    if (lane < PP) g_nids[warp*PP + lane] = paths[((size_t)t*LL + leaf)*PP + lane];
    if (lane == 0) g_active[warp] = anyp;
}

// ---------------------------------------------------------------------------
__global__ void __launch_bounds__(NTHR, 1)
lstm_mma(const float* __restrict__ node_emb, float* __restrict__ out) {
    extern __shared__ __align__(16) char smem[];
    const uint32_t sb = smem_u32(smem);
    const int tid  = threadIdx.x;
    const int wid  = tid >> 5, lane = tid & 31;
    const int g    = lane >> 2, tg = lane & 3;
    const int mw   = wid >> 3, nw = wid & 7;        // 2 x 8 warp grid
    const int bt0  = blockIdx.x * MROWS;

    int* snid   = (int*)(smem + SM_NID);
    int* sact   = (int*)(smem + SM_ACT);
    float* sbias = (float*)(smem + SM_BIAS);
    for (int i = tid; i < MROWS*PP; i += NTHR) snid[i] = g_nids[bt0*PP + i];
    for (int i = tid; i < MROWS; i += NTHR)    sact[i] = g_active[bt0 + i];
    for (int i = tid; i < NG; i += NTHR)       sbias[i] = g_bias[i];
    if (tid == 0) { mbar_init(sb + SM_MBAR, 1); mbar_init(sb + SM_MBAR + 8, 1); }
    __syncthreads();

    // per-lane ldmatrix offset within any A tile (mi=0, k8=0)
    const uint32_t lrow = (lane & 7) + ((lane & 8) ? 8 : 0);
    const uint32_t lcol = (lane & 16) ? 16u : 0u;
    const uint32_t aoff = (mw*64 + lrow) * ROWB + lcol;
    const uint32_t ax_b  = sb + SM_AX  + aoff;
    const uint32_t ahi_b = sb + SM_AHI + aoff;
    const uint32_t alo_b = sb + SM_ALO + aoff;

    const int rbase = mw*64 + g + ((tg & 1) ? 8 : 0);   // epilogue row base

    float creg[4][8], hk[4][8];
#pragma unroll
    for (int q = 0; q < 4; q++)
#pragma unroll
        for (int i = 0; i < 8; i++) creg[q][i] = 0.0f;

    int icnt = 0, ccnt = 0;

    auto issue = [&](int cid) {
        if (tid == 0) {
            uint32_t mb = sb + SM_MBAR + 8*(icnt & 1);
            mbar_expect_tx(mb, CHUNK);
            bulk_g2s(sb + SM_W + (icnt & 1)*CHUNK,
                     (const char*)g_Bimg + (size_t)cid*CHUNK, CHUNK, mb);
        }
        icnt++;
    };
    auto wait_buf = [&]() -> const char* {
        mbar_wait(sb + SM_MBAR + 8*(ccnt & 1), (ccnt >> 1) & 1);
        const char* w = smem + SM_W + (ccnt & 1)*CHUNK;
        ccnt++;
        return w;
    };

    for (int p = 0; p < PP; p++) {
        // ---- gather x_p into A_x ----
#pragma unroll
        for (int i = 0; i < 8; i++) {
            int idx = i * NTHR + tid;          // 4096 float4 items
            int mm = idx >> 5, kq = (idx & 31) << 2;
            const float4 v = *(const float4*)(node_emb + (size_t)snid[mm*PP + p]*DD + kq);
            __nv_bfloat162 a = __floats2bfloat162_rn(v.x, v.y);
            __nv_bfloat162 b = __floats2bfloat162_rn(v.z, v.w);
            uint2 pk; pk.x = *(uint32_t*)&a; pk.y = *(uint32_t*)&b;
            *(uint2*)(smem + SM_AX + mm*ROWB + kq*2) = pk;
        }
        __syncthreads();   // x visible; prev h scatter visible; W bufs free

        if (p == 0) issue(0); else issue(0);   // chunk 0 either way

#pragma unroll
        for (int q = 0; q < 4; q++) {
            float d[4][2][4];
            if (p == 0) {
                if (q < 3) issue((q + 1) * 3);
                const char* W = wait_buf();
#pragma unroll
                for (int mi = 0; mi < 4; mi++)
#pragma unroll
                    for (int ni = 0; ni < 2; ni++)
#pragma unroll
                        for (int e = 0; e < 4; e++) d[mi][ni][e] = 0.0f;
                gemm_pass(ax_b, W, nw, g, tg, d);
                __syncthreads();
            } else {
#pragma unroll
                for (int part = 0; part < 3; part++) {
                    const int ci = q*3 + part;
                    if (ci + 1 < 12) issue(ci + 1);
                    const char* W = wait_buf();
                    if (part == 0) {
#pragma unroll
                        for (int mi = 0; mi < 4; mi++)
#pragma unroll
                            for (int ni = 0; ni < 2; ni++)
#pragma unroll
                                for (int e = 0; e < 4; e++) d[mi][ni][e] = 0.0f;
                        gemm_pass(ax_b, W, nw, g, tg, d);
                    } else if (part == 1) {
                        gemm_pass(ahi_b, W, nw, g, tg, d);
                        gemm_pass(alo_b, W, nw, g, tg, d);
                    } else {
                        gemm_pass(ahi_b, W, nw, g, tg, d);
                    }
                    __syncthreads();
                }
            }
            // ---- epilogue for quarter q (static indices) ----
#pragma unroll
            for (int ni = 0; ni < 2; ni++) {
                const int j = q*32 + nw*4 + ni*2 + (tg >> 1);
                const float bi = sbias[j],       bfv = sbias[128 + j];
                const float bg = sbias[256 + j], bo  = sbias[384 + j];
#pragma unroll
                for (int mi = 0; mi < 4; mi++) {
                    float d0 = d[mi][ni][0], d1 = d[mi][ni][1];
                    float d2 = d[mi][ni][2], d3 = d[mi][ni][3];
                    float s0 = __shfl_xor_sync(0xffffffffu, d0, 1);
                    float s1 = __shfl_xor_sync(0xffffffffu, d1, 1);
                    float s2 = __shfl_xor_sync(0xffffffffu, d2, 1);
                    float s3 = __shfl_xor_sync(0xffffffffu, d3, 1);
                    float gi, gf, gg, go;
                    if ((tg & 1) == 0) { gi = d0; gf = d1; gg = s0; go = s1; }
                    else               { gi = s2; gf = s3; gg = d2; go = d3; }
                    float& cc = creg[q][mi*2 + ni];
                    cc = sigf(gf + bfv) * cc + sigf(gi + bi) * tanhf_(gg + bg);
                    hk[q][mi*2 + ni] = sigf(go + bo) * tanhf_(cc);
                }
            }
        }

        if (p < PP - 1) {
            // scatter h -> A_hi / A_lo for next step (safe: all warps past last barrier)
#pragma unroll
            for (int q = 0; q < 4; q++)
#pragma unroll
                for (int ni = 0; ni < 2; ni++) {
                    const int j = q*32 + nw*4 + ni*2 + (tg >> 1);
#pragma unroll
                    for (int mi = 0; mi < 4; mi++) {
                        const int r = rbase + mi*16;
                        float h = hk[q][mi*2 + ni];
                        __nv_bfloat16 hi = __float2bfloat16(h);
                        *(__nv_bfloat16*)(smem + SM_AHI + r*ROWB + j*2) = hi;
                        *(__nv_bfloat16*)(smem + SM_ALO + r*ROWB + j*2) =
                            __float2bfloat16(h - __bfloat162float(hi));
                    }
                }
        }
    }

    // ---- final output: stage fp32 h, then coalesced write ----
    float* stage = (float*)smem;
#pragma unroll
    for (int q = 0; q < 4; q++)
#pragma unroll
        for (int ni = 0; ni < 2; ni++) {
            const int j = q*32 + nw*4 + ni*2 + (tg >> 1);
#pragma unroll
            for (int mi = 0; mi < 4; mi++)
                stage[(rbase + mi*16)*129 + j] = hk[q][mi*2 + ni];
        }
    __syncthreads();
#pragma unroll 4
    for (int i = tid; i < MROWS*DD; i += NTHR) {
        int r = i >> 7, k = i & 127;
        out[(size_t)(bt0 + r)*DD + k] = sact[r] ? stage[r*129 + k] : 0.0f;
    }
}

// ---------------------------------------------------------------------------
extern "C" void kernel_launch(void* const* d_in, const int* in_sizes, int n_in,
                              void* d_out, int out_size) {
    const float* cross    = (const float*)d_in[0];
    const float* node_emb = (const float*)d_in[1];
    const float* w_ih     = (const float*)d_in[2];
    const float* w_hh     = (const float*)d_in[3];
    const float* b_ih     = (const float*)d_in[4];
    const float* b_hh     = (const float*)d_in[5];
    const int*   paths    = (const int*)d_in[6];
    float* out = (float*)d_out;

    cudaFuncSetAttribute(lstm_mma, cudaFuncAttributeMaxDynamicSharedMemorySize, SMEM_SZ);
    prep_kernel<<<(3*NG*DD + 255)/256, 256>>>(w_ih, w_hh, b_ih, b_hh);
    leaf_kernel<<<(NSEQ*32 + 127)/128, 128>>>(cross, paths);
    lstm_mma<<<NBLK, NTHR, SMEM_SZ>>>(node_emb, out);
}

// round 8
// speedup vs baseline: 5.4215x; 1.1507x over previous
#include <cuda_runtime.h>
#include <cuda_bf16.h>
#include <cstdint>

#define BB   512
#define TT   100
#define LL   256
#define DD   128
#define PP   9
#define NSEQ (BB*TT)
#define NG   512
#define MROWS 128
#define NBLK (NSEQ/MROWS)   // 400
#define NTHR 512
#define ROWB  272            // padded row stride bytes
#define CHUNK (128*ROWB)     // 34816 bytes
#define NCHUNKS 8            // q*2 + {0:Wih, 1:Whh}

// SMEM layout (dynamic)
#define SM_AX   0
#define SM_AHI  34816
#define SM_ALO  69632
#define SM_W    104448       // 3 x CHUNK ring
#define SM_BIAS 208896
#define SM_NID  210944
#define SM_ACT  215552
#define SM_MBAR 216064       // 3 mbars
#define SMEM_SZ 216192

__device__ __align__(128) unsigned char g_Bimg[NCHUNKS*CHUNK];
__device__ float g_bias[NG];
__device__ int   g_nids[NSEQ*PP];
__device__ int   g_active[NSEQ];

__device__ __forceinline__ float sigf(float x)   { return 1.0f / (1.0f + __expf(-x)); }
__device__ __forceinline__ float tanhf_(float x) { return 1.0f - 2.0f / (__expf(2.0f*x) + 1.0f); }

__device__ __forceinline__ uint32_t smem_u32(const void* p) {
    uint32_t a;
    asm("{ .reg .u64 t; cvta.to.shared.u64 t, %1; cvt.u32.u64 %0, t; }" : "=r"(a) : "l"(p));
    return a;
}
__device__ __forceinline__ void mbar_init(uint32_t mbar, uint32_t cnt) {
    asm volatile("mbarrier.init.shared.b64 [%0], %1;" :: "r"(mbar), "r"(cnt) : "memory");
}
__device__ __forceinline__ void mbar_expect_tx(uint32_t mbar, uint32_t bytes) {
    asm volatile("mbarrier.arrive.expect_tx.shared.b64 _, [%0], %1;" :: "r"(mbar), "r"(bytes) : "memory");
}
__device__ __forceinline__ void mbar_wait(uint32_t mbar, uint32_t ph) {
    asm volatile(
        "{\n\t.reg .pred P;\n\tLW_%=:\n\t"
        "mbarrier.try_wait.parity.acquire.cta.shared::cta.b64 P, [%0], %1, 0x989680;\n\t"
        "@P bra LD_%=;\n\tbra LW_%=;\n\tLD_%=:\n\t}"
        :: "r"(mbar), "r"(ph) : "memory");
}
__device__ __forceinline__ void bulk_g2s(uint32_t dst, const void* src, uint32_t bytes, uint32_t mbar) {
    asm volatile(
        "cp.async.bulk.shared::cluster.global.mbarrier::complete_tx::bytes [%0], [%1], %2, [%3];"
        :: "r"(dst), "l"(src), "r"(bytes), "r"(mbar) : "memory");
}
__device__ __forceinline__ void mma16816(float* d, const uint32_t* a, const uint32_t* b) {
    asm volatile(
        "mma.sync.aligned.m16n8k16.row.col.f32.bf16.bf16.f32 "
        "{%0,%1,%2,%3}, {%4,%5,%6,%7}, {%8,%9}, {%0,%1,%2,%3};"
        : "+f"(d[0]), "+f"(d[1]), "+f"(d[2]), "+f"(d[3])
        : "r"(a[0]), "r"(a[1]), "r"(a[2]), "r"(a[3]), "r"(b[0]), "r"(b[1]));
}
__device__ __forceinline__ void ldsm4(uint32_t* r, uint32_t addr) {
    asm volatile("ldmatrix.sync.aligned.m8n8.x4.shared.b16 {%0,%1,%2,%3}, [%4];"
        : "=r"(r[0]), "=r"(r[1]), "=r"(r[2]), "=r"(r[3]) : "r"(addr));
}

// One [64m x 16n x 128k] warp product-accumulate.
__device__ __forceinline__ void gemm_pass(uint32_t abase, const char* __restrict__ W,
                                          int nw, int g, int tg, float d[4][2][4]) {
#pragma unroll
    for (int k8 = 0; k8 < 8; k8++) {
        uint32_t a[4][4], b[2][2];
#pragma unroll
        for (int mi = 0; mi < 4; mi++)
            ldsm4(a[mi], abase + mi*(16*ROWB) + k8*32);
        const int kb = (k8*16 + tg*2) * 2;
#pragma unroll
        for (int ni = 0; ni < 2; ni++) {
            const char* wr = W + (nw*16 + ni*8 + g)*ROWB + kb;
            b[ni][0] = *(const uint32_t*)wr;
            b[ni][1] = *(const uint32_t*)(wr + 16);
        }
#pragma unroll
        for (int mi = 0; mi < 4; mi++)
#pragma unroll
            for (int ni = 0; ni < 2; ni++)
                mma16816(d[mi][ni], a[mi], b[ni]);
    }
}

// ---------------------------------------------------------------------------
// prep: chunk = q*2 + part (0:Wih, 1:Whh bf16); row n=(j&31)*4+gate, 272B rows
// ---------------------------------------------------------------------------
__global__ void prep_kernel(const float* __restrict__ w_ih, const float* __restrict__ w_hh,
                            const float* __restrict__ b_ih, const float* __restrict__ b_hh) {
    int idx = blockIdx.x * blockDim.x + threadIdx.x;
    if (idx < NG) g_bias[idx] = b_ih[idx] + b_hh[idx];
    if (idx >= 2 * NG * DD) return;
    int part = idx >> 16;
    int rem  = idx & 65535;
    int r = rem >> 7;
    int k = rem & 127;
    int gate = r >> 7, j = r & 127;
    int q = j >> 5;
    int n = ((j & 31) << 2) | gate;
    float w = (part == 0) ? w_ih[r * DD + k] : w_hh[r * DD + k];
    *(__nv_bfloat16*)((char*)g_Bimg + (q*2 + part)*CHUNK + n*ROWB + k*2) = __float2bfloat16(w);
}

// ---------------------------------------------------------------------------
__global__ void leaf_kernel(const float* __restrict__ cross, const int* __restrict__ paths) {
    int warp = (blockIdx.x * blockDim.x + threadIdx.x) >> 5;
    int lane = threadIdx.x & 31;
    if (warp >= NSEQ) return;
    int b = warp / TT;
    int t = warp - b * TT;
    const float* row = cross + (size_t)b * (TT*LL) + (size_t)t * LL;
    float bv = -3.0e38f; int bl = 0; int anyp = 0;
#pragma unroll
    for (int i = 0; i < LL/32; i++) {
        int l = lane + 32*i;
        float v = row[l];
        if (v > 0.0f) anyp = 1;
        if (v > bv) { bv = v; bl = l; }
    }
#pragma unroll
    for (int off = 16; off > 0; off >>= 1) {
        float ov = __shfl_down_sync(0xffffffffu, bv, off);
        int   ol = __shfl_down_sync(0xffffffffu, bl, off);
        if (ov > bv || (ov == bv && ol < bl)) { bv = ov; bl = ol; }
    }
    anyp = __any_sync(0xffffffffu, anyp);
    int leaf = __shfl_sync(0xffffffffu, bl, 0);
    if (lane < PP) g_nids[warp*PP + lane] = paths[((size_t)t*LL + leaf)*PP + lane];
    if (lane == 0) g_active[warp] = anyp;
}

// ---------------------------------------------------------------------------
__global__ void __launch_bounds__(NTHR, 1)
lstm_mma(const float* __restrict__ node_emb, float* __restrict__ out) {
    extern __shared__ __align__(16) char smem[];
    const uint32_t sb = smem_u32(smem);
    const int tid  = threadIdx.x;
    const int wid  = tid >> 5, lane = tid & 31;
    const int g    = lane >> 2, tg = lane & 3;
    const int mw   = wid >> 3, nw = wid & 7;        // 2 x 8 warp grid
    const int bt0  = blockIdx.x * MROWS;

    int* snid   = (int*)(smem + SM_NID);
    int* sact   = (int*)(smem + SM_ACT);
    float* sbias = (float*)(smem + SM_BIAS);
    for (int i = tid; i < MROWS*PP; i += NTHR) snid[i] = g_nids[bt0*PP + i];
    for (int i = tid; i < MROWS; i += NTHR)    sact[i] = g_active[bt0 + i];
    for (int i = tid; i < NG; i += NTHR)       sbias[i] = g_bias[i];
    if (tid == 0) {
        mbar_init(sb + SM_MBAR, 1);
        mbar_init(sb + SM_MBAR + 8, 1);
        mbar_init(sb + SM_MBAR + 16, 1);
    }
    __syncthreads();

    // per-lane ldmatrix offset within any A tile (mi=0, k8=0)
    const uint32_t lrow = (lane & 7) + ((lane & 8) ? 8 : 0);
    const uint32_t lcol = (lane & 16) ? 16u : 0u;
    const uint32_t aoff = (mw*64 + lrow) * ROWB + lcol;
    const uint32_t ax_b  = sb + SM_AX  + aoff;
    const uint32_t ahi_b = sb + SM_AHI + aoff;
    const uint32_t alo_b = sb + SM_ALO + aoff;

    const int rbase = mw*64 + g + ((tg & 1) ? 8 : 0);   // epilogue row base

    float creg[4][8], hk[4][8];
#pragma unroll
    for (int q = 0; q < 4; q++)
#pragma unroll
        for (int i = 0; i < 8; i++) creg[q][i] = 0.0f;

    int icnt = 0, ccnt = 0;

    auto issue = [&](int cid) {
        if (tid == 0) {
            uint32_t mb = sb + SM_MBAR + 8*(icnt % 3);
            mbar_expect_tx(mb, CHUNK);
            bulk_g2s(sb + SM_W + (icnt % 3)*CHUNK,
                     (const char*)g_Bimg + (size_t)cid*CHUNK, CHUNK, mb);
        }
        icnt++;
    };
    auto wait_buf = [&]() -> const char* {
        mbar_wait(sb + SM_MBAR + 8*(ccnt % 3), (ccnt / 3) & 1);
        const char* w = smem + SM_W + (ccnt % 3)*CHUNK;
        ccnt++;
        return w;
    };

    for (int p = 0; p < PP; p++) {
        const int L = (p == 0) ? 4 : 8;
        int inext = 0;
        // issue first 3 chunks BEFORE gather -> transfers overlap the x gather
        for (int ii = 0; ii < 3 && ii < L; ii++) {
            issue((p == 0) ? 2*inext : inext);
            inext++;
        }

        // ---- gather x_p into A_x ----
#pragma unroll
        for (int i = 0; i < 8; i++) {
            int idx = i * NTHR + tid;          // 4096 float4 items
            int mm = idx >> 5, kq = (idx & 31) << 2;
            const float4 v = *(const float4*)(node_emb + (size_t)snid[mm*PP + p]*DD + kq);
            __nv_bfloat162 a = __floats2bfloat162_rn(v.x, v.y);
            __nv_bfloat162 b = __floats2bfloat162_rn(v.z, v.w);
            uint2 pk; pk.x = *(uint32_t*)&a; pk.y = *(uint32_t*)&b;
            *(uint2*)(smem + SM_AX + mm*ROWB + kq*2) = pk;
        }
        __syncthreads();   // x + prev h scatter visible

#pragma unroll
        for (int q = 0; q < 4; q++) {
            float d[4][2][4];
#pragma unroll
            for (int mi = 0; mi < 4; mi++)
#pragma unroll
                for (int ni = 0; ni < 2; ni++)
#pragma unroll
                    for (int e = 0; e < 4; e++) d[mi][ni][e] = 0.0f;

            {   // x-part: chunk q*2 (Wih)
                const char* W = wait_buf();
                gemm_pass(ax_b, W, nw, g, tg, d);
                __syncthreads();
                if (inext < L) { issue((p == 0) ? 2*inext : inext); inext++; }
            }
            if (p > 0) {   // h-part: chunk q*2+1 (Whh), hi + lo passes
                const char* W = wait_buf();
                gemm_pass(ahi_b, W, nw, g, tg, d);
                gemm_pass(alo_b, W, nw, g, tg, d);
                __syncthreads();
                if (inext < L) { issue(inext); inext++; }
            }

            // ---- epilogue for quarter q (overlaps incoming transfers) ----
#pragma unroll
            for (int ni = 0; ni < 2; ni++) {
                const int j = q*32 + nw*4 + ni*2 + (tg >> 1);
                const float bi = sbias[j],       bfv = sbias[128 + j];
                const float bg = sbias[256 + j], bo  = sbias[384 + j];
#pragma unroll
                for (int mi = 0; mi < 4; mi++) {
                    float d0 = d[mi][ni][0], d1 = d[mi][ni][1];
                    float d2 = d[mi][ni][2], d3 = d[mi][ni][3];
                    float s0 = __shfl_xor_sync(0xffffffffu, d0, 1);
                    float s1 = __shfl_xor_sync(0xffffffffu, d1, 1);
                    float s2 = __shfl_xor_sync(0xffffffffu, d2, 1);
                    float s3 = __shfl_xor_sync(0xffffffffu, d3, 1);
                    float gi, gf, gg, go;
                    if ((tg & 1) == 0) { gi = d0; gf = d1; gg = s0; go = s1; }
                    else               { gi = s2; gf = s3; gg = d2; go = d3; }
                    float& cc = creg[q][mi*2 + ni];
                    cc = sigf(gf + bfv) * cc + sigf(gi + bi) * tanhf_(gg + bg);
                    hk[q][mi*2 + ni] = sigf(go + bo) * tanhf_(cc);
                }
            }
        }

        if (p < PP - 1) {
            // scatter h -> A_hi / A_lo for next step (all reads done: post last sync)
#pragma unroll
            for (int q = 0; q < 4; q++)
#pragma unroll
                for (int ni = 0; ni < 2; ni++) {
                    const int j = q*32 + nw*4 + ni*2 + (tg >> 1);
#pragma unroll
                    for (int mi = 0; mi < 4; mi++) {
                        const int r = rbase + mi*16;
                        float h = hk[q][mi*2 + ni];
                        __nv_bfloat16 hi = __float2bfloat16(h);
                        *(__nv_bfloat16*)(smem + SM_AHI + r*ROWB + j*2) = hi;
                        *(__nv_bfloat16*)(smem + SM_ALO + r*ROWB + j*2) =
                            __float2bfloat16(h - __bfloat162float(hi));
                    }
                }
        }
    }

    // ---- final output: stage fp32 h, then coalesced write ----
    float* stage = (float*)smem;
#pragma unroll
    for (int q = 0; q < 4; q++)
#pragma unroll
        for (int ni = 0; ni < 2; ni++) {
            const int j = q*32 + nw*4 + ni*2 + (tg >> 1);
#pragma unroll
            for (int mi = 0; mi < 4; mi++)
                stage[(rbase + mi*16)*129 + j] = hk[q][mi*2 + ni];
        }
    __syncthreads();
#pragma unroll 4
    for (int i = tid; i < MROWS*DD; i += NTHR) {
        int r = i >> 7, k = i & 127;
        out[(size_t)(bt0 + r)*DD + k] = sact[r] ? stage[r*129 + k] : 0.0f;
    }
}

// ---------------------------------------------------------------------------
extern "C" void kernel_launch(void* const* d_in, const int* in_sizes, int n_in,
                              void* d_out, int out_size) {
    const float* cross    = (const float*)d_in[0];
    const float* node_emb = (const float*)d_in[1];
    const float* w_ih     = (const float*)d_in[2];
    const float* w_hh     = (const float*)d_in[3];
    const float* b_ih     = (const float*)d_in[4];
    const float* b_hh     = (const float*)d_in[5];
    const int*   paths    = (const int*)d_in[6];
    float* out = (float*)d_out;

    cudaFuncSetAttribute(lstm_mma, cudaFuncAttributeMaxDynamicSharedMemorySize, SMEM_SZ);
    prep_kernel<<<(2*NG*DD + 255)/256, 256>>>(w_ih, w_hh, b_ih, b_hh);
    leaf_kernel<<<(NSEQ*32 + 127)/128, 128>>>(cross, paths);
    lstm_mma<<<NBLK, NTHR, SMEM_SZ>>>(node_emb, out);
}